// round 11
// baseline (speedup 1.0000x reference)
#include <cuda_runtime.h>
#include <cuda_bf16.h>
#include <cstdint>

#define D        128
#define N_INIT   100000
#define LVLS     64
#define M        4096
#define N_RULES  256
#define N_TOT    (N_INIT + LVLS * M)

#define NCTA     256           // persistent CTAs = rules, 2 per SM, single wave
#define TILE_N   32
#define EVAL_BLOCKS 256

#define BPITCH_B 528
#define WIMG_BYTES 65536

__device__ float g_store[(size_t)N_TOT * D];
__device__ float g_logit[N_TOT];                 // raw dot(emb, eval_w), no bias
__device__ int   g_order[LVLS * M];
__device__ int   g_ruleoff[LVLS * (N_RULES + 1)];
__device__ int4  g_pack[LVLS * M];               // (j, p0, p1, 0) per grouped slot
__device__ float g_partial[EVAL_BLOCKS * 6];
__device__ unsigned g_grp[16];
__device__ unsigned g_root;
__device__ unsigned g_epoch;
__device__ unsigned char g_WimgHi[(size_t)N_RULES * WIMG_BYTES];
__device__ unsigned char g_WimgLo[(size_t)N_RULES * WIMG_BYTES];

static __device__ __forceinline__ unsigned pack_bf16x2(float lo, float hi) {
    unsigned short a = __bfloat16_as_ushort(__float2bfloat16_rn(lo));
    unsigned short b = __bfloat16_as_ushort(__float2bfloat16_rn(hi));
    return (unsigned)a | ((unsigned)b << 16);
}
static __device__ __forceinline__ float bf16_hi_part(float v) {
    return __bfloat162float(__float2bfloat16_rn(v));
}

// ---------------------------------------------------------------------------
// K1: init embeddings (warp per node) + fused eval dot -> g_logit
// ---------------------------------------------------------------------------
__global__ void init_embed_kernel(const float4* __restrict__ thax,
                                  const float4* __restrict__ sine,
                                  const int* __restrict__ it,
                                  const int* __restrict__ is,
                                  const float* __restrict__ eval_w)
{
    int wid  = threadIdx.x >> 5;
    int lane = threadIdx.x & 31;
    int gw     = blockIdx.x * 8 + wid;
    int nwarps = gridDim.x * 8;
    float4 w4 = ((const float4*)eval_w)[lane];
    float4* st = (float4*)g_store;

    for (int i = gw; i < N_INIT; i += nwarps) {
        float4 a = thax[(size_t)__ldg(it + i) * 32 + lane];
        float4 b = sine[(size_t)__ldg(is + i) * 32 + lane];
        float4 e = make_float4(a.x + b.x, a.y + b.y, a.z + b.z, a.w + b.w);
        st[(size_t)i * 32 + lane] = e;
        float d = e.x * w4.x + e.y * w4.y + e.z * w4.z + e.w * w4.w;
        #pragma unroll
        for (int off = 16; off; off >>= 1) d += __shfl_down_sync(0xffffffffu, d, off);
        if (lane == 0) g_logit[i] = d;
    }
}

// ---------------------------------------------------------------------------
// K1b: convert rule_W -> fragment-ordered bf16 hi/lo images (separate planes).
// ---------------------------------------------------------------------------
__global__ void convw_kernel(const float* __restrict__ rule_W)
{
    extern __shared__ float Wsm[];            // [256][128]
    int r   = blockIdx.x;
    int tid = threadIdx.x;

    const float4* src = (const float4*)(rule_W + (size_t)r * 32768);
    #pragma unroll 4
    for (int i = tid; i < 8192; i += 256) ((float4*)Wsm)[i] = __ldg(src + i);
    __syncthreads();

    unsigned char* dh = g_WimgHi + (size_t)r * WIMG_BYTES;
    unsigned char* dl = g_WimgLo + (size_t)r * WIMG_BYTES;
    for (int idx = tid; idx < 4096; idx += 256) {
        int lane = idx & 31, kk = (idx >> 5) & 15, w = idx >> 9;
        int m0 = w * 16 + (lane >> 2);
        int k0 = kk * 16 + (lane & 3) * 2;

        float v[8];
        v[0] = Wsm[(k0)     * 128 + m0];     v[1] = Wsm[(k0 + 1) * 128 + m0];
        v[2] = Wsm[(k0)     * 128 + m0 + 8]; v[3] = Wsm[(k0 + 1) * 128 + m0 + 8];
        v[4] = Wsm[(k0 + 8) * 128 + m0];     v[5] = Wsm[(k0 + 9) * 128 + m0];
        v[6] = Wsm[(k0 + 8) * 128 + m0 + 8]; v[7] = Wsm[(k0 + 9) * 128 + m0 + 8];

        unsigned h[4], l[4];
        #pragma unroll
        for (int j = 0; j < 4; j++) {
            float h0 = bf16_hi_part(v[2*j]),   h1 = bf16_hi_part(v[2*j+1]);
            h[j] = pack_bf16x2(h0, h1);
            l[j] = pack_bf16x2(v[2*j] - h0, v[2*j+1] - h1);
        }
        *(uint4*)(dh + (size_t)idx * 16) = make_uint4(h[0], h[1], h[2], h[3]);
        *(uint4*)(dl + (size_t)idx * 16) = make_uint4(l[0], l[1], l[2], l[3]);
    }
}

// ---------------------------------------------------------------------------
// K2: group by rule + pack (j,p0,p1) + offsets + reset barrier
// ---------------------------------------------------------------------------
__global__ void group_kernel(const int* __restrict__ rules,
                             const int* __restrict__ parents)
{
    int lvl = blockIdx.x;
    int tid = threadIdx.x;
    __shared__ int counts[N_RULES];
    __shared__ int offs[N_RULES + 1];
    __shared__ int cursor[N_RULES];

    if (lvl == 0) {           // reset tree-barrier state each replay
        if (tid < 16) g_grp[tid] = 0;
        if (tid == 16) g_root = 0;
        if (tid == 17) g_epoch = 0;
    }

    for (int r = tid; r < N_RULES; r += blockDim.x) counts[r] = 0;
    __syncthreads();
    for (int j = tid; j < M; j += blockDim.x)
        atomicAdd(&counts[rules[lvl * M + j]], 1);
    __syncthreads();
    if (tid == 0) {
        int s = 0;
        for (int r = 0; r < N_RULES; r++) { offs[r] = s; s += counts[r]; }
        offs[N_RULES] = s;
    }
    __syncthreads();
    for (int r = tid; r < N_RULES; r += blockDim.x) cursor[r] = offs[r];
    for (int r = tid; r <= N_RULES; r += blockDim.x)
        g_ruleoff[lvl * (N_RULES + 1) + r] = offs[r];
    __syncthreads();
    for (int j = tid; j < M; j += blockDim.x) {
        int r = rules[lvl * M + j];
        int p = atomicAdd(&cursor[r], 1);
        g_order[lvl * M + p] = j;
    }
    __syncthreads();

    for (int slot = tid; slot < M; slot += blockDim.x) {
        int j = g_order[lvl * M + slot];
        int4 pk;
        pk.x = j;
        pk.y = parents[((size_t)lvl * M + j) * 2 + 0];
        pk.z = parents[((size_t)lvl * M + j) * 2 + 1];
        pk.w = 0;
        g_pack[lvl * M + slot] = pk;
    }
}

// ---------------------------------------------------------------------------
// mma helpers
// ---------------------------------------------------------------------------
static __device__ __forceinline__ void mma16816(float* c, const uint4& a,
                                                unsigned b0, unsigned b1)
{
    asm volatile(
        "mma.sync.aligned.m16n8k16.row.col.f32.bf16.bf16.f32 "
        "{%0,%1,%2,%3}, {%4,%5,%6,%7}, {%8,%9}, {%0,%1,%2,%3};"
        : "+f"(c[0]), "+f"(c[1]), "+f"(c[2]), "+f"(c[3])
        : "r"(a.x), "r"(a.y), "r"(a.z), "r"(a.w), "r"(b0), "r"(b1));
}
static __device__ __forceinline__ void ldmat4(unsigned& r0, unsigned& r1,
                                              unsigned& r2, unsigned& r3, unsigned addr)
{
    asm volatile("ldmatrix.sync.aligned.m8n8.x4.shared.b16 {%0,%1,%2,%3}, [%4];"
                 : "=r"(r0), "=r"(r1), "=r"(r2), "=r"(r3) : "r"(addr));
}
static __device__ __forceinline__ uint4 ldg_cg16(const uint4* p)
{
    uint4 v;
    asm volatile("ld.global.cg.v4.u32 {%0,%1,%2,%3}, [%4];"
                 : "=r"(v.x), "=r"(v.y), "=r"(v.z), "=r"(v.w) : "l"(p));
    return v;
}

// combined tree barrier (16 groups x 16 CTAs) — EXACT R7 protocol
__device__ __forceinline__ void grid_barrier(unsigned target)
{
    __syncthreads();
    if (threadIdx.x == 0) {
        __threadfence();
        unsigned g = blockIdx.x >> 4;
        unsigned v = atomicAdd(&g_grp[g], 1u);
        if ((v & 15u) == 15u) {
            unsigned rr = atomicAdd(&g_root, 1u);
            if ((rr & 15u) == 15u) atomicAdd(&g_epoch, 1u);
        }
        while (*((volatile unsigned*)&g_epoch) < target) __nanosleep(32);
        __threadfence();
    }
    __syncthreads();
}

// NB = number of active 8-node blocks (1..4); 3-term split-bf16
template<int NB>
static __device__ __forceinline__ void tile_compute(
    const uint4* __restrict__ ahp,
    const uint4* __restrict__ alp,
    unsigned bh_base, unsigned bl_base,
    unsigned lm_off_p0, unsigned lm_off_p1,
    float acc[4][4])
{
    #pragma unroll 4
    for (int kk = 0; kk < 16; kk++) {
        uint4 ah = __ldg(ahp);          // L1-resident (pinned rule)
        uint4 al = ldg_cg16(alp);       // L2 stream
        ahp += 32; alp += 32;
        unsigned kb = (unsigned)kk * 32;

        unsigned bh0, bh1, bh2, bh3, bl0, bl1, bl2, bl3;
        ldmat4(bh0, bh1, bh2, bh3, bh_base + lm_off_p0 + kb);
        ldmat4(bl0, bl1, bl2, bl3, bl_base + lm_off_p0 + kb);
        mma16816(acc[0], ah, bh0, bh1);
        mma16816(acc[0], ah, bl0, bl1);
        mma16816(acc[0], al, bh0, bh1);
        if (NB > 1) {
            mma16816(acc[1], ah, bh2, bh3);
            mma16816(acc[1], ah, bl2, bl3);
            mma16816(acc[1], al, bh2, bh3);
        }
        if (NB > 2) {
            unsigned ch0, ch1, ch2, ch3, cl0, cl1, cl2, cl3;
            ldmat4(ch0, ch1, ch2, ch3, bh_base + lm_off_p1 + kb);
            ldmat4(cl0, cl1, cl2, cl3, bl_base + lm_off_p1 + kb);
            mma16816(acc[2], ah, ch0, ch1);
            mma16816(acc[2], ah, cl0, cl1);
            mma16816(acc[2], al, ch0, ch1);
            if (NB > 3) {
                mma16816(acc[3], ah, ch2, ch3);
                mma16816(acc[3], ah, cl2, cl3);
                mma16816(acc[3], al, ch2, ch3);
            }
        }
    }
}

// ---------------------------------------------------------------------------
// K3: persistent levels kernel (R7 structure) + fused logit epilogue
// ---------------------------------------------------------------------------
__global__ void __launch_bounds__(256, 2)
levels_kernel(const float* __restrict__ rule_b,
              const float* __restrict__ eval_w)
{
    __shared__ __align__(16) unsigned char Bh[TILE_N * BPITCH_B];
    __shared__ __align__(16) unsigned char Bl[TILE_N * BPITCH_B];
    __shared__ int s_meta[96];
    __shared__ float s_part[8][32];   // per-warp logit partials

    int tid  = threadIdx.x;
    int wid  = tid >> 5;
    int lane = tid & 31;
    int r    = blockIdx.x;           // pinned rule

    unsigned bh_base = (unsigned)__cvta_generic_to_shared(Bh);
    unsigned bl_base = (unsigned)__cvta_generic_to_shared(Bl);

    int g    = lane >> 3;
    int row8 = lane & 7;
    unsigned lm_koff   = (unsigned)(g & 1) * 16;
    unsigned lm_off_p0 = (unsigned)((0 * 2 + (g >> 1)) * 8 + row8) * BPITCH_B + lm_koff;
    unsigned lm_off_p1 = (unsigned)((1 * 2 + (g >> 1)) * 8 + row8) * BPITCH_B + lm_koff;

    const uint4* ahi0 = (const uint4*)(g_WimgHi + (size_t)r * WIMG_BYTES)
                        + (size_t)wid * 512 + lane;
    const uint4* alo0 = (const uint4*)(g_WimgLo + (size_t)r * WIMG_BYTES)
                        + (size_t)wid * 512 + lane;

    int m_lo = wid * 16 + (lane >> 2);
    int m_hi = m_lo + 8;
    float bias_lo = __ldg(rule_b + r * 128 + m_lo);
    float bias_hi = __ldg(rule_b + r * 128 + m_hi);

    for (int lvl = 0; lvl < LVLS; lvl++) {
        int start = g_ruleoff[lvl * (N_RULES + 1) + r];
        int end   = g_ruleoff[lvl * (N_RULES + 1) + r + 1];

        for (int tb = start; tb < end; tb += TILE_N) {
            int nact = min(TILE_N, end - tb);

            if (tid < TILE_N) {
                int4 pk = (tid < nact) ? g_pack[lvl * M + tb + tid]
                                       : make_int4(-1, 0, 0, 0);
                s_meta[tid] = pk.x; s_meta[32 + tid] = pk.y; s_meta[64 + tid] = pk.z;
            }
            __syncthreads();

            // PE gather + split-bf16 into Bh/Bl ([n][k] row-major, pitch 528B)
            {
                int s   = tid >> 3;        // node 0..31
                int seg = tid & 7;         // 32-k segment
                int j = s_meta[s];
                if (j >= 0) {
                    int p    = (seg < 4) ? s_meta[32 + s] : s_meta[64 + s];
                    int poff = (seg & 3) * 32;
                    const float4* src = (const float4*)(g_store + (size_t)p * D + poff);
                    unsigned char* dh = Bh + s * BPITCH_B + seg * 64;
                    unsigned char* dl = Bl + s * BPITCH_B + seg * 64;
                    #pragma unroll
                    for (int q = 0; q < 8; q += 2) {
                        float4 f0 = __ldcg(src + q);
                        float4 f1 = __ldcg(src + q + 1);
                        float h0x = bf16_hi_part(f0.x), h0y = bf16_hi_part(f0.y);
                        float h0z = bf16_hi_part(f0.z), h0w = bf16_hi_part(f0.w);
                        float h1x = bf16_hi_part(f1.x), h1y = bf16_hi_part(f1.y);
                        float h1z = bf16_hi_part(f1.z), h1w = bf16_hi_part(f1.w);
                        *(uint2*)(dh + q * 8) =
                            make_uint2(pack_bf16x2(h0x, h0y), pack_bf16x2(h0z, h0w));
                        *(uint2*)(dh + q * 8 + 8) =
                            make_uint2(pack_bf16x2(h1x, h1y), pack_bf16x2(h1z, h1w));
                        *(uint2*)(dl + q * 8) =
                            make_uint2(pack_bf16x2(f0.x - h0x, f0.y - h0y),
                                       pack_bf16x2(f0.z - h0z, f0.w - h0w));
                        *(uint2*)(dl + q * 8 + 8) =
                            make_uint2(pack_bf16x2(f1.x - h1x, f1.y - h1y),
                                       pack_bf16x2(f1.z - h1z, f1.w - h1w));
                    }
                }
            }
            __syncthreads();

            // compute + store + logit partial
            {
                float acc[4][4];
                #pragma unroll
                for (int nb = 0; nb < 4; nb++)
                    #pragma unroll
                    for (int q = 0; q < 4; q++) acc[nb][q] = 0.0f;

                int nblk = (nact + 7) >> 3;
                switch (nblk) {
                    case 4: tile_compute<4>(ahi0, alo0, bh_base, bl_base, lm_off_p0, lm_off_p1, acc); break;
                    case 3: tile_compute<3>(ahi0, alo0, bh_base, bl_base, lm_off_p0, lm_off_p1, acc); break;
                    case 2: tile_compute<2>(ahi0, alo0, bh_base, bl_base, lm_off_p0, lm_off_p1, acc); break;
                    default: tile_compute<1>(ahi0, alo0, bh_base, bl_base, lm_off_p0, lm_off_p1, acc); break;
                }

                size_t lvlbase = (size_t)N_INIT + (size_t)lvl * M;
                float wlo = __ldg(eval_w + m_lo);
                float whi = __ldg(eval_w + m_hi);

                #pragma unroll
                for (int nb = 0; nb < 4; nb++) {
                    float p0 = 0.0f, p1 = 0.0f;
                    if (nb < nblk) {
                        int n0 = nb * 8 + (lane & 3) * 2;
                        int j0 = s_meta[n0], j1 = s_meta[n0 + 1];
                        if (j0 >= 0) {
                            float x0 = fmaxf(acc[nb][0] + bias_lo, 0.f);
                            float x2 = fmaxf(acc[nb][2] + bias_hi, 0.f);
                            g_store[(lvlbase + j0) * D + m_lo] = x0;
                            g_store[(lvlbase + j0) * D + m_hi] = x2;
                            p0 = wlo * x0 + whi * x2;
                        }
                        if (j1 >= 0) {
                            float x1 = fmaxf(acc[nb][1] + bias_lo, 0.f);
                            float x3 = fmaxf(acc[nb][3] + bias_hi, 0.f);
                            g_store[(lvlbase + j1) * D + m_lo] = x1;
                            g_store[(lvlbase + j1) * D + m_hi] = x3;
                            p1 = wlo * x1 + whi * x3;
                        }
                    }
                    // same-(lane&3) shfl tree: offsets 16, 8, 4
                    #pragma unroll
                    for (int off = 16; off >= 4; off >>= 1) {
                        p0 += __shfl_down_sync(0xffffffffu, p0, off);
                        p1 += __shfl_down_sync(0xffffffffu, p1, off);
                    }
                    if (lane < 4) {
                        s_part[wid][nb * 8 + lane * 2]     = p0;
                        s_part[wid][nb * 8 + lane * 2 + 1] = p1;
                    }
                }
                __syncthreads();
                if (tid < 32) {
                    int j = s_meta[tid];
                    if (j >= 0) {
                        float ssum = 0.0f;
                        #pragma unroll
                        for (int w = 0; w < 8; w++) ssum += s_part[w][tid];
                        g_logit[lvlbase + j] = ssum;
                    }
                }
            }
            __syncthreads();   // done with Bh/Bl/meta/s_part before next tile
        }
        if (lvl != LVLS - 1) grid_barrier((unsigned)(lvl + 1));
    }
}

// ---------------------------------------------------------------------------
// K4: eval over precomputed logits (4.3 MB instead of 186 MB)
// ---------------------------------------------------------------------------
__global__ void eval_kernel(const float* __restrict__ eval_b,
                            const float* __restrict__ pos_vals,
                            const float* __restrict__ neg_vals)
{
    __shared__ float wacc[8][6];
    int tid  = threadIdx.x;
    int wid  = tid >> 5;
    int lane = tid & 31;
    int gt     = blockIdx.x * 256 + tid;
    int stride = EVAL_BLOCKS * 256;
    float eb = eval_b[0];

    float A = 0.f, B = 0.f, pok = 0.f, nok = 0.f, spv = 0.f, snv = 0.f;

    for (int node = gt; node < N_TOT; node += stride) {
        float l  = g_logit[node] + eb;
        float pv = pos_vals[node], nv = neg_vals[node];
        float spn = log1pf(expf(-fabsf(l)));
        float sp_pos = spn + fmaxf(l, 0.f);
        float sp_neg = spn + fmaxf(-l, 0.f);
        A += pv * sp_neg;
        B += nv * sp_pos;
        if (l >= 0.f) pok += pv; else nok += nv;
        spv += pv;
        snv += nv;
    }

    #pragma unroll
    for (int off = 16; off; off >>= 1) {
        A   += __shfl_down_sync(0xffffffffu, A, off);
        B   += __shfl_down_sync(0xffffffffu, B, off);
        pok += __shfl_down_sync(0xffffffffu, pok, off);
        nok += __shfl_down_sync(0xffffffffu, nok, off);
        spv += __shfl_down_sync(0xffffffffu, spv, off);
        snv += __shfl_down_sync(0xffffffffu, snv, off);
    }
    if (lane == 0) {
        wacc[wid][0] = A;   wacc[wid][1] = B;
        wacc[wid][2] = pok; wacc[wid][3] = nok;
        wacc[wid][4] = spv; wacc[wid][5] = snv;
    }
    __syncthreads();
    if (tid == 0) {
        float o[6] = {0, 0, 0, 0, 0, 0};
        for (int w = 0; w < 8; w++)
            for (int k = 0; k < 6; k++) o[k] += wacc[w][k];
        for (int k = 0; k < 6; k++) g_partial[blockIdx.x * 6 + k] = o[k];
    }
}

__global__ void final_kernel(float* __restrict__ out)
{
    if (blockIdx.x == 0 && threadIdx.x == 0) {
        float A = 0.f, B = 0.f, pok = 0.f, nok = 0.f, spv = 0.f, snv = 0.f;
        for (int b = 0; b < EVAL_BLOCKS; b++) {
            A   += g_partial[b * 6 + 0];
            B   += g_partial[b * 6 + 1];
            pok += g_partial[b * 6 + 2];
            nok += g_partial[b * 6 + 3];
            spv += g_partial[b * 6 + 4];
            snv += g_partial[b * 6 + 5];
        }
        float pw = snv / spv;
        out[0] = pw * A + B;
        out[1] = pok;
        out[2] = nok;
    }
}

// ---------------------------------------------------------------------------
extern "C" void kernel_launch(void* const* d_in, const int* in_sizes, int n_in,
                              void* d_out, int out_size)
{
    const float* thax_table = (const float*)d_in[0];
    const float* sine_table = (const float*)d_in[1];
    const float* rule_W     = (const float*)d_in[2];
    const float* rule_b     = (const float*)d_in[3];
    const float* eval_w     = (const float*)d_in[4];
    const float* eval_b     = (const float*)d_in[5];
    const float* pos_vals   = (const float*)d_in[6];
    const float* neg_vals   = (const float*)d_in[7];
    const int*   init_thax  = (const int*)d_in[8];
    const int*   init_sine  = (const int*)d_in[9];
    const int*   parents    = (const int*)d_in[10];
    const int*   rules      = (const int*)d_in[11];

    (void)in_sizes; (void)n_in; (void)out_size;

    cudaFuncSetAttribute(convw_kernel,
                         cudaFuncAttributeMaxDynamicSharedMemorySize, 131072);

    init_embed_kernel<<<2048, 256>>>((const float4*)thax_table,
                                     (const float4*)sine_table,
                                     init_thax, init_sine, eval_w);
    convw_kernel<<<N_RULES, 256, 131072>>>(rule_W);
    group_kernel<<<LVLS, 256>>>(rules, parents);
    levels_kernel<<<NCTA, 256>>>(rule_b, eval_w);
    eval_kernel<<<EVAL_BLOCKS, 256>>>(eval_b, pos_vals, neg_vals);
    final_kernel<<<1, 32>>>((float*)d_out);
}

// round 12
// speedup vs baseline: 1.6552x; 1.6552x over previous
#include <cuda_runtime.h>
#include <cuda_bf16.h>
#include <cstdint>

#define D        128
#define N_INIT   100000
#define LVLS     64
#define M        4096
#define N_RULES  256
#define N_TOT    (N_INIT + LVLS * M)
#define N_DERIV  (LVLS * M)

#define NCTA     256           // persistent CTAs = rules, 2 per SM, single wave
#define TILE_N   32
#define EVAL_BLOCKS 1024

#define BPITCH_B 528
#define WIMG_BYTES 65536

__device__ float g_store[(size_t)N_TOT * D];
__device__ int   g_order[LVLS * M];
__device__ int   g_ruleoff[LVLS * (N_RULES + 1)];
__device__ int4  g_pack[LVLS * M];               // (j, p0, p1, 0) per grouped slot
__device__ unsigned g_ready[N_DERIV];            // per derived node ready flag
__device__ float g_partial[EVAL_BLOCKS * 6];
__device__ unsigned char g_WimgHi[(size_t)N_RULES * WIMG_BYTES];
__device__ unsigned char g_WimgLo[(size_t)N_RULES * WIMG_BYTES];

static __device__ __forceinline__ unsigned pack_bf16x2(float lo, float hi) {
    unsigned short a = __bfloat16_as_ushort(__float2bfloat16_rn(lo));
    unsigned short b = __bfloat16_as_ushort(__float2bfloat16_rn(hi));
    return (unsigned)a | ((unsigned)b << 16);
}
static __device__ __forceinline__ float bf16_hi_part(float v) {
    return __bfloat162float(__float2bfloat16_rn(v));
}

// ---------------------------------------------------------------------------
// K1: init embeddings
// ---------------------------------------------------------------------------
__global__ void init_embed_kernel(const float4* __restrict__ thax,
                                  const float4* __restrict__ sine,
                                  const int* __restrict__ it,
                                  const int* __restrict__ is)
{
    int tid = blockIdx.x * blockDim.x + threadIdx.x;
    int total = N_INIT * (D / 4);
    float4* st = (float4*)g_store;
    for (int k = tid; k < total; k += gridDim.x * blockDim.x) {
        int i = k >> 5;
        int c = k & 31;
        float4 a = thax[(size_t)it[i] * 32 + c];
        float4 b = sine[(size_t)is[i] * 32 + c];
        st[(size_t)i * 32 + c] = make_float4(a.x + b.x, a.y + b.y, a.z + b.z, a.w + b.w);
    }
}

// ---------------------------------------------------------------------------
// K1b: convert rule_W -> fragment-ordered bf16 hi/lo images (separate planes).
// ---------------------------------------------------------------------------
__global__ void convw_kernel(const float* __restrict__ rule_W)
{
    extern __shared__ float Wsm[];            // [256][128]
    int r   = blockIdx.x;
    int tid = threadIdx.x;

    const float4* src = (const float4*)(rule_W + (size_t)r * 32768);
    #pragma unroll 4
    for (int i = tid; i < 8192; i += 256) ((float4*)Wsm)[i] = __ldg(src + i);
    __syncthreads();

    unsigned char* dh = g_WimgHi + (size_t)r * WIMG_BYTES;
    unsigned char* dl = g_WimgLo + (size_t)r * WIMG_BYTES;
    for (int idx = tid; idx < 4096; idx += 256) {
        int lane = idx & 31, kk = (idx >> 5) & 15, w = idx >> 9;
        int m0 = w * 16 + (lane >> 2);
        int k0 = kk * 16 + (lane & 3) * 2;

        float v[8];
        v[0] = Wsm[(k0)     * 128 + m0];     v[1] = Wsm[(k0 + 1) * 128 + m0];
        v[2] = Wsm[(k0)     * 128 + m0 + 8]; v[3] = Wsm[(k0 + 1) * 128 + m0 + 8];
        v[4] = Wsm[(k0 + 8) * 128 + m0];     v[5] = Wsm[(k0 + 9) * 128 + m0];
        v[6] = Wsm[(k0 + 8) * 128 + m0 + 8]; v[7] = Wsm[(k0 + 9) * 128 + m0 + 8];

        unsigned h[4], l[4];
        #pragma unroll
        for (int j = 0; j < 4; j++) {
            float h0 = bf16_hi_part(v[2*j]),   h1 = bf16_hi_part(v[2*j+1]);
            h[j] = pack_bf16x2(h0, h1);
            l[j] = pack_bf16x2(v[2*j] - h0, v[2*j+1] - h1);
        }
        *(uint4*)(dh + (size_t)idx * 16) = make_uint4(h[0], h[1], h[2], h[3]);
        *(uint4*)(dl + (size_t)idx * 16) = make_uint4(l[0], l[1], l[2], l[3]);
    }
}

// ---------------------------------------------------------------------------
// K2: group by rule + pack (j,p0,p1) + offsets + zero ready flags
// ---------------------------------------------------------------------------
__global__ void group_kernel(const int* __restrict__ rules,
                             const int* __restrict__ parents)
{
    int lvl = blockIdx.x;
    int tid = threadIdx.x;
    __shared__ int counts[N_RULES];
    __shared__ int offs[N_RULES + 1];
    __shared__ int cursor[N_RULES];

    // zero this level's ready flags (fresh each replay)
    for (int j = tid; j < M; j += blockDim.x) g_ready[lvl * M + j] = 0;

    for (int r = tid; r < N_RULES; r += blockDim.x) counts[r] = 0;
    __syncthreads();
    for (int j = tid; j < M; j += blockDim.x)
        atomicAdd(&counts[rules[lvl * M + j]], 1);
    __syncthreads();
    if (tid == 0) {
        int s = 0;
        for (int r = 0; r < N_RULES; r++) { offs[r] = s; s += counts[r]; }
        offs[N_RULES] = s;
    }
    __syncthreads();
    for (int r = tid; r < N_RULES; r += blockDim.x) cursor[r] = offs[r];
    for (int r = tid; r <= N_RULES; r += blockDim.x)
        g_ruleoff[lvl * (N_RULES + 1) + r] = offs[r];
    __syncthreads();
    for (int j = tid; j < M; j += blockDim.x) {
        int r = rules[lvl * M + j];
        int p = atomicAdd(&cursor[r], 1);
        g_order[lvl * M + p] = j;
    }
    __syncthreads();

    for (int slot = tid; slot < M; slot += blockDim.x) {
        int j = g_order[lvl * M + slot];
        int4 pk;
        pk.x = j;
        pk.y = parents[((size_t)lvl * M + j) * 2 + 0];
        pk.z = parents[((size_t)lvl * M + j) * 2 + 1];
        pk.w = 0;
        g_pack[lvl * M + slot] = pk;
    }
}

// ---------------------------------------------------------------------------
// mma helpers
// ---------------------------------------------------------------------------
static __device__ __forceinline__ void mma16816(float* c, const uint4& a,
                                                unsigned b0, unsigned b1)
{
    asm volatile(
        "mma.sync.aligned.m16n8k16.row.col.f32.bf16.bf16.f32 "
        "{%0,%1,%2,%3}, {%4,%5,%6,%7}, {%8,%9}, {%0,%1,%2,%3};"
        : "+f"(c[0]), "+f"(c[1]), "+f"(c[2]), "+f"(c[3])
        : "r"(a.x), "r"(a.y), "r"(a.z), "r"(a.w), "r"(b0), "r"(b1));
}
static __device__ __forceinline__ void ldmat4(unsigned& r0, unsigned& r1,
                                              unsigned& r2, unsigned& r3, unsigned addr)
{
    asm volatile("ldmatrix.sync.aligned.m8n8.x4.shared.b16 {%0,%1,%2,%3}, [%4];"
                 : "=r"(r0), "=r"(r1), "=r"(r2), "=r"(r3) : "r"(addr));
}
static __device__ __forceinline__ uint4 ldg_cg16(const uint4* p)
{
    uint4 v;
    asm volatile("ld.global.cg.v4.u32 {%0,%1,%2,%3}, [%4];"
                 : "=r"(v.x), "=r"(v.y), "=r"(v.z), "=r"(v.w) : "l"(p));
    return v;
}

// NB = number of active 8-node blocks (1..4); 3-term split-bf16
template<int NB>
static __device__ __forceinline__ void tile_compute(
    const uint4* __restrict__ ahp,
    const uint4* __restrict__ alp,
    unsigned bh_base, unsigned bl_base,
    unsigned lm_off_p0, unsigned lm_off_p1,
    float acc[4][4])
{
    #pragma unroll 4
    for (int kk = 0; kk < 16; kk++) {
        uint4 ah = __ldg(ahp);          // L1-resident (pinned rule)
        uint4 al = ldg_cg16(alp);       // L2 stream
        ahp += 32; alp += 32;
        unsigned kb = (unsigned)kk * 32;

        unsigned bh0, bh1, bh2, bh3, bl0, bl1, bl2, bl3;
        ldmat4(bh0, bh1, bh2, bh3, bh_base + lm_off_p0 + kb);
        ldmat4(bl0, bl1, bl2, bl3, bl_base + lm_off_p0 + kb);
        mma16816(acc[0], ah, bh0, bh1);
        mma16816(acc[0], ah, bl0, bl1);
        mma16816(acc[0], al, bh0, bh1);
        if (NB > 1) {
            mma16816(acc[1], ah, bh2, bh3);
            mma16816(acc[1], ah, bl2, bl3);
            mma16816(acc[1], al, bh2, bh3);
        }
        if (NB > 2) {
            unsigned ch0, ch1, ch2, ch3, cl0, cl1, cl2, cl3;
            ldmat4(ch0, ch1, ch2, ch3, bh_base + lm_off_p1 + kb);
            ldmat4(cl0, cl1, cl2, cl3, bl_base + lm_off_p1 + kb);
            mma16816(acc[2], ah, ch0, ch1);
            mma16816(acc[2], ah, cl0, cl1);
            mma16816(acc[2], al, ch0, ch1);
            if (NB > 3) {
                mma16816(acc[3], ah, ch2, ch3);
                mma16816(acc[3], ah, cl2, cl3);
                mma16816(acc[3], al, ch2, ch3);
            }
        }
    }
}

// ---------------------------------------------------------------------------
// K3: persistent levels kernel — dataflow sync via per-node ready flags
// ---------------------------------------------------------------------------
__global__ void __launch_bounds__(256, 2)
levels_kernel(const float* __restrict__ rule_b)
{
    __shared__ __align__(16) unsigned char Bh[TILE_N * BPITCH_B];
    __shared__ __align__(16) unsigned char Bl[TILE_N * BPITCH_B];
    __shared__ int s_meta[96];

    int tid  = threadIdx.x;
    int wid  = tid >> 5;
    int lane = tid & 31;
    int r    = blockIdx.x;           // pinned rule

    unsigned bh_base = (unsigned)__cvta_generic_to_shared(Bh);
    unsigned bl_base = (unsigned)__cvta_generic_to_shared(Bl);

    int g    = lane >> 3;
    int row8 = lane & 7;
    unsigned lm_koff   = (unsigned)(g & 1) * 16;
    unsigned lm_off_p0 = (unsigned)((0 * 2 + (g >> 1)) * 8 + row8) * BPITCH_B + lm_koff;
    unsigned lm_off_p1 = (unsigned)((1 * 2 + (g >> 1)) * 8 + row8) * BPITCH_B + lm_koff;

    const uint4* ahi0 = (const uint4*)(g_WimgHi + (size_t)r * WIMG_BYTES)
                        + (size_t)wid * 512 + lane;
    const uint4* alo0 = (const uint4*)(g_WimgLo + (size_t)r * WIMG_BYTES)
                        + (size_t)wid * 512 + lane;

    int m_lo = wid * 16 + (lane >> 2);
    int m_hi = m_lo + 8;
    float bias_lo = __ldg(rule_b + r * 128 + m_lo);
    float bias_hi = __ldg(rule_b + r * 128 + m_hi);

    for (int lvl = 0; lvl < LVLS; lvl++) {
        int start = g_ruleoff[lvl * (N_RULES + 1) + r];
        int end   = g_ruleoff[lvl * (N_RULES + 1) + r + 1];

        for (int tb = start; tb < end; tb += TILE_N) {
            int nact = min(TILE_N, end - tb);

            if (tid < TILE_N) {
                int4 pk = (tid < nact) ? g_pack[lvl * M + tb + tid]
                                       : make_int4(-1, 0, 0, 0);
                s_meta[tid] = pk.x; s_meta[32 + tid] = pk.y; s_meta[64 + tid] = pk.z;
            }
            __syncthreads();

            // dataflow wait: poll ready flags of derived parents
            if (tid < 64) {
                int j = s_meta[tid & 31];
                int p = s_meta[32 + tid];
                if (j >= 0 && p >= N_INIT) {
                    const unsigned* f = &g_ready[p - N_INIT];
                    unsigned v;
                    for (;;) {
                        asm volatile("ld.global.cg.u32 %0, [%1];" : "=r"(v) : "l"(f));
                        if (v) break;
                        __nanosleep(20);
                    }
                }
            }
            __syncthreads();   // CTA-scope acquire: all parents ready before gather

            // PE gather + split-bf16 into Bh/Bl ([n][k] row-major, pitch 528B)
            {
                int s   = tid >> 3;        // node 0..31
                int seg = tid & 7;         // 32-k segment
                int j = s_meta[s];
                if (j >= 0) {
                    int p    = (seg < 4) ? s_meta[32 + s] : s_meta[64 + s];
                    int poff = (seg & 3) * 32;
                    const float4* src = (const float4*)(g_store + (size_t)p * D + poff);
                    unsigned char* dh = Bh + s * BPITCH_B + seg * 64;
                    unsigned char* dl = Bl + s * BPITCH_B + seg * 64;
                    #pragma unroll
                    for (int q = 0; q < 8; q += 2) {
                        float4 f0 = __ldcg(src + q);
                        float4 f1 = __ldcg(src + q + 1);
                        float h0x = bf16_hi_part(f0.x), h0y = bf16_hi_part(f0.y);
                        float h0z = bf16_hi_part(f0.z), h0w = bf16_hi_part(f0.w);
                        float h1x = bf16_hi_part(f1.x), h1y = bf16_hi_part(f1.y);
                        float h1z = bf16_hi_part(f1.z), h1w = bf16_hi_part(f1.w);
                        *(uint2*)(dh + q * 8) =
                            make_uint2(pack_bf16x2(h0x, h0y), pack_bf16x2(h0z, h0w));
                        *(uint2*)(dh + q * 8 + 8) =
                            make_uint2(pack_bf16x2(h1x, h1y), pack_bf16x2(h1z, h1w));
                        *(uint2*)(dl + q * 8) =
                            make_uint2(pack_bf16x2(f0.x - h0x, f0.y - h0y),
                                       pack_bf16x2(f0.z - h0z, f0.w - h0w));
                        *(uint2*)(dl + q * 8 + 8) =
                            make_uint2(pack_bf16x2(f1.x - h1x, f1.y - h1y),
                                       pack_bf16x2(f1.z - h1z, f1.w - h1w));
                    }
                }
            }
            __syncthreads();

            // compute: warp wid -> output rows 16*wid..+15; skip dead n-blocks
            {
                float acc[4][4];
                #pragma unroll
                for (int nb = 0; nb < 4; nb++)
                    #pragma unroll
                    for (int q = 0; q < 4; q++) acc[nb][q] = 0.0f;

                int nblk = (nact + 7) >> 3;
                switch (nblk) {
                    case 4: tile_compute<4>(ahi0, alo0, bh_base, bl_base, lm_off_p0, lm_off_p1, acc); break;
                    case 3: tile_compute<3>(ahi0, alo0, bh_base, bl_base, lm_off_p0, lm_off_p1, acc); break;
                    case 2: tile_compute<2>(ahi0, alo0, bh_base, bl_base, lm_off_p0, lm_off_p1, acc); break;
                    default: tile_compute<1>(ahi0, alo0, bh_base, bl_base, lm_off_p0, lm_off_p1, acc); break;
                }

                size_t lvlbase = (size_t)N_INIT + (size_t)lvl * M;
                #pragma unroll
                for (int nb = 0; nb < 4; nb++) {
                    if (nb < nblk) {
                        int n0 = nb * 8 + (lane & 3) * 2;
                        int j0 = s_meta[n0], j1 = s_meta[n0 + 1];
                        if (j0 >= 0) {
                            g_store[(lvlbase + j0) * D + m_lo] = fmaxf(acc[nb][0] + bias_lo, 0.f);
                            g_store[(lvlbase + j0) * D + m_hi] = fmaxf(acc[nb][2] + bias_hi, 0.f);
                        }
                        if (j1 >= 0) {
                            g_store[(lvlbase + j1) * D + m_lo] = fmaxf(acc[nb][1] + bias_lo, 0.f);
                            g_store[(lvlbase + j1) * D + m_hi] = fmaxf(acc[nb][3] + bias_hi, 0.f);
                        }
                    }
                }
            }

            // publish: make stores visible, then set ready flags
            __threadfence();
            __syncthreads();
            if (tid < TILE_N) {
                int j = s_meta[tid];
                if (j >= 0) {
                    asm volatile("st.global.cg.u32 [%0], %1;"
                                 :: "l"(&g_ready[lvl * M + j]), "r"(1u) : "memory");
                }
            }
            __syncthreads();   // protect s_meta/Bh/Bl before next tile
        }
    }
}

// ---------------------------------------------------------------------------
// K4: eval + partial reductions
// ---------------------------------------------------------------------------
__global__ void eval_kernel(const float* __restrict__ eval_w,
                            const float* __restrict__ eval_b,
                            const float* __restrict__ pos_vals,
                            const float* __restrict__ neg_vals)
{
    __shared__ float4 sw[32];
    __shared__ float  wacc[8][6];
    if (threadIdx.x < 32) sw[threadIdx.x] = ((const float4*)eval_w)[threadIdx.x];
    __syncthreads();

    int wid  = threadIdx.x >> 5;
    int lane = threadIdx.x & 31;
    int gw     = blockIdx.x * 8 + wid;
    int nwarps = EVAL_BLOCKS * 8;
    float eb = eval_b[0];
    float4 w4 = sw[lane];

    float A = 0.f, B = 0.f, pok = 0.f, nok = 0.f, spv = 0.f, snv = 0.f;

    for (size_t node = gw; node < (size_t)N_TOT; node += nwarps) {
        float4 v = ((const float4*)(g_store + node * D))[lane];
        float d = v.x * w4.x + v.y * w4.y + v.z * w4.z + v.w * w4.w;
        #pragma unroll
        for (int off = 16; off; off >>= 1) d += __shfl_down_sync(0xffffffffu, d, off);
        if (lane == 0) {
            float l  = d + eb;
            float pv = pos_vals[node], nv = neg_vals[node];
            float spn = log1pf(expf(-fabsf(l)));
            float sp_pos = spn + fmaxf(l, 0.f);
            float sp_neg = spn + fmaxf(-l, 0.f);
            A += pv * sp_neg;
            B += nv * sp_pos;
            if (l >= 0.f) pok += pv; else nok += nv;
            spv += pv;
            snv += nv;
        }
    }

    if (lane == 0) {
        wacc[wid][0] = A;   wacc[wid][1] = B;
        wacc[wid][2] = pok; wacc[wid][3] = nok;
        wacc[wid][4] = spv; wacc[wid][5] = snv;
    }
    __syncthreads();
    if (threadIdx.x == 0) {
        float o[6] = {0, 0, 0, 0, 0, 0};
        for (int w = 0; w < 8; w++)
            for (int k = 0; k < 6; k++) o[k] += wacc[w][k];
        for (int k = 0; k < 6; k++) g_partial[blockIdx.x * 6 + k] = o[k];
    }
}

__global__ void final_kernel(float* __restrict__ out)
{
    if (blockIdx.x == 0 && threadIdx.x == 0) {
        float A = 0.f, B = 0.f, pok = 0.f, nok = 0.f, spv = 0.f, snv = 0.f;
        for (int b = 0; b < EVAL_BLOCKS; b++) {
            A   += g_partial[b * 6 + 0];
            B   += g_partial[b * 6 + 1];
            pok += g_partial[b * 6 + 2];
            nok += g_partial[b * 6 + 3];
            spv += g_partial[b * 6 + 4];
            snv += g_partial[b * 6 + 5];
        }
        float pw = snv / spv;
        out[0] = pw * A + B;
        out[1] = pok;
        out[2] = nok;
    }
}

// ---------------------------------------------------------------------------
extern "C" void kernel_launch(void* const* d_in, const int* in_sizes, int n_in,
                              void* d_out, int out_size)
{
    const float* thax_table = (const float*)d_in[0];
    const float* sine_table = (const float*)d_in[1];
    const float* rule_W     = (const float*)d_in[2];
    const float* rule_b     = (const float*)d_in[3];
    const float* eval_w     = (const float*)d_in[4];
    const float* eval_b     = (const float*)d_in[5];
    const float* pos_vals   = (const float*)d_in[6];
    const float* neg_vals   = (const float*)d_in[7];
    const int*   init_thax  = (const int*)d_in[8];
    const int*   init_sine  = (const int*)d_in[9];
    const int*   parents    = (const int*)d_in[10];
    const int*   rules      = (const int*)d_in[11];

    (void)in_sizes; (void)n_in; (void)out_size;

    cudaFuncSetAttribute(convw_kernel,
                         cudaFuncAttributeMaxDynamicSharedMemorySize, 131072);

    init_embed_kernel<<<2048, 256>>>((const float4*)thax_table,
                                     (const float4*)sine_table,
                                     init_thax, init_sine);
    convw_kernel<<<N_RULES, 256, 131072>>>(rule_W);
    group_kernel<<<LVLS, 256>>>(rules, parents);
    levels_kernel<<<NCTA, 256>>>(rule_b);
    eval_kernel<<<EVAL_BLOCKS, 256>>>(eval_w, eval_b, pos_vals, neg_vals);
    final_kernel<<<1, 32>>>((float*)d_out);
}

// round 14
// speedup vs baseline: 1.6563x; 1.0006x over previous
#include <cuda_runtime.h>
#include <cuda_bf16.h>
#include <cstdint>

#define D        128
#define N_INIT   100000
#define LVLS     64
#define M        4096
#define N_RULES  256
#define N_TOT    (N_INIT + LVLS * M)
#define N_DERIV  (LVLS * M)

#define NCTA     256           // persistent CTAs = rules, 2 per SM, single wave
#define TILE_N   32
#define MAXT_R   96            // max tiles per rule
#define EVAL_BLOCKS 1024

#define BPITCH_B 528
#define WIMG_BYTES 65536

__device__ float g_store[(size_t)N_TOT * D];
__device__ __align__(16) unsigned short g_hi[(size_t)N_TOT * D];
__device__ __align__(16) unsigned short g_lo[(size_t)N_TOT * D];
__device__ int   g_order[LVLS * M];
__device__ int   g_ruleoff[LVLS * (N_RULES + 1)];
__device__ int4  g_pack[LVLS * M];               // (global node, p0, p1, 0)
__device__ int   g_tiles[N_RULES * MAXT_R];      // (slotbase << 6) | nact
__device__ int   g_ntiles[N_RULES];
__device__ unsigned g_ready[N_DERIV];
__device__ float g_partial[EVAL_BLOCKS * 6];
__device__ unsigned char g_WimgHi[(size_t)N_RULES * WIMG_BYTES];
__device__ unsigned char g_WimgLo[(size_t)N_RULES * WIMG_BYTES];

static __device__ __forceinline__ unsigned pack_bf16x2(float lo, float hi) {
    unsigned short a = __bfloat16_as_ushort(__float2bfloat16_rn(lo));
    unsigned short b = __bfloat16_as_ushort(__float2bfloat16_rn(hi));
    return (unsigned)a | ((unsigned)b << 16);
}
static __device__ __forceinline__ float bf16_hi_part(float v) {
    return __bfloat162float(__float2bfloat16_rn(v));
}
static __device__ __forceinline__ unsigned short bf16_us(float v) {
    return __bfloat16_as_ushort(__float2bfloat16_rn(v));
}

// ---------------------------------------------------------------------------
// K1: init embeddings (warp per node) + hi/lo planes
// ---------------------------------------------------------------------------
__global__ void init_embed_kernel(const float4* __restrict__ thax,
                                  const float4* __restrict__ sine,
                                  const int* __restrict__ it,
                                  const int* __restrict__ is)
{
    int wid  = threadIdx.x >> 5;
    int lane = threadIdx.x & 31;
    int gw     = blockIdx.x * 8 + wid;
    int nwarps = gridDim.x * 8;
    float4* st = (float4*)g_store;

    for (int i = gw; i < N_INIT; i += nwarps) {
        float4 a = thax[(size_t)__ldg(it + i) * 32 + lane];
        float4 b = sine[(size_t)__ldg(is + i) * 32 + lane];
        float4 e = make_float4(a.x + b.x, a.y + b.y, a.z + b.z, a.w + b.w);
        st[(size_t)i * 32 + lane] = e;
        float hx = bf16_hi_part(e.x), hy = bf16_hi_part(e.y);
        float hz = bf16_hi_part(e.z), hw = bf16_hi_part(e.w);
        *(uint2*)(g_hi + (size_t)i * D + lane * 4) =
            make_uint2(pack_bf16x2(hx, hy), pack_bf16x2(hz, hw));
        *(uint2*)(g_lo + (size_t)i * D + lane * 4) =
            make_uint2(pack_bf16x2(e.x - hx, e.y - hy), pack_bf16x2(e.z - hz, e.w - hw));
    }
}

// ---------------------------------------------------------------------------
// K1b: convert rule_W -> fragment-ordered bf16 hi/lo images
// ---------------------------------------------------------------------------
__global__ void convw_kernel(const float* __restrict__ rule_W)
{
    extern __shared__ float Wsm[];            // [256][128]
    int r   = blockIdx.x;
    int tid = threadIdx.x;

    const float4* src = (const float4*)(rule_W + (size_t)r * 32768);
    #pragma unroll 4
    for (int i = tid; i < 8192; i += 256) ((float4*)Wsm)[i] = __ldg(src + i);
    __syncthreads();

    unsigned char* dh = g_WimgHi + (size_t)r * WIMG_BYTES;
    unsigned char* dl = g_WimgLo + (size_t)r * WIMG_BYTES;
    for (int idx = tid; idx < 4096; idx += 256) {
        int lane = idx & 31, kk = (idx >> 5) & 15, w = idx >> 9;
        int m0 = w * 16 + (lane >> 2);
        int k0 = kk * 16 + (lane & 3) * 2;

        float v[8];
        v[0] = Wsm[(k0)     * 128 + m0];     v[1] = Wsm[(k0 + 1) * 128 + m0];
        v[2] = Wsm[(k0)     * 128 + m0 + 8]; v[3] = Wsm[(k0 + 1) * 128 + m0 + 8];
        v[4] = Wsm[(k0 + 8) * 128 + m0];     v[5] = Wsm[(k0 + 9) * 128 + m0];
        v[6] = Wsm[(k0 + 8) * 128 + m0 + 8]; v[7] = Wsm[(k0 + 9) * 128 + m0 + 8];

        unsigned h[4], l[4];
        #pragma unroll
        for (int j = 0; j < 4; j++) {
            float h0 = bf16_hi_part(v[2*j]),   h1 = bf16_hi_part(v[2*j+1]);
            h[j] = pack_bf16x2(h0, h1);
            l[j] = pack_bf16x2(v[2*j] - h0, v[2*j+1] - h1);
        }
        *(uint4*)(dh + (size_t)idx * 16) = make_uint4(h[0], h[1], h[2], h[3]);
        *(uint4*)(dl + (size_t)idx * 16) = make_uint4(l[0], l[1], l[2], l[3]);
    }
}

// ---------------------------------------------------------------------------
// K2: group by rule + pack (global node, p0, p1) + offsets + zero flags
// ---------------------------------------------------------------------------
__global__ void group_kernel(const int* __restrict__ rules,
                             const int* __restrict__ parents)
{
    int lvl = blockIdx.x;
    int tid = threadIdx.x;
    __shared__ int counts[N_RULES];
    __shared__ int offs[N_RULES + 1];
    __shared__ int cursor[N_RULES];

    for (int j = tid; j < M; j += blockDim.x) g_ready[lvl * M + j] = 0;

    for (int r = tid; r < N_RULES; r += blockDim.x) counts[r] = 0;
    __syncthreads();
    for (int j = tid; j < M; j += blockDim.x)
        atomicAdd(&counts[rules[lvl * M + j]], 1);
    __syncthreads();
    if (tid == 0) {
        int s = 0;
        for (int r = 0; r < N_RULES; r++) { offs[r] = s; s += counts[r]; }
        offs[N_RULES] = s;
    }
    __syncthreads();
    for (int r = tid; r < N_RULES; r += blockDim.x) cursor[r] = offs[r];
    for (int r = tid; r <= N_RULES; r += blockDim.x)
        g_ruleoff[lvl * (N_RULES + 1) + r] = offs[r];
    __syncthreads();
    for (int j = tid; j < M; j += blockDim.x) {
        int r = rules[lvl * M + j];
        int p = atomicAdd(&cursor[r], 1);
        g_order[lvl * M + p] = j;
    }
    __syncthreads();

    for (int slot = tid; slot < M; slot += blockDim.x) {
        int j = g_order[lvl * M + slot];
        int4 pk;
        pk.x = N_INIT + lvl * M + j;             // global node id
        pk.y = parents[((size_t)lvl * M + j) * 2 + 0];
        pk.z = parents[((size_t)lvl * M + j) * 2 + 1];
        pk.w = 0;
        g_pack[lvl * M + slot] = pk;
    }
}

// K2b: flat per-rule tile list
__global__ void tiles_kernel()
{
    int r = threadIdx.x;
    if (r < N_RULES) {
        int cnt = 0;
        for (int lvl = 0; lvl < LVLS; lvl++) {
            int st = g_ruleoff[lvl * (N_RULES + 1) + r];
            int en = g_ruleoff[lvl * (N_RULES + 1) + r + 1];
            for (int tb = st; tb < en; tb += TILE_N) {
                int na = min(TILE_N, en - tb);
                g_tiles[r * MAXT_R + cnt] = ((lvl * M + tb) << 6) | na;
                cnt++;
            }
        }
        g_ntiles[r] = cnt;
    }
}

// ---------------------------------------------------------------------------
// mma helpers
// ---------------------------------------------------------------------------
static __device__ __forceinline__ void mma16816(float* c, const uint4& a,
                                                unsigned b0, unsigned b1)
{
    asm volatile(
        "mma.sync.aligned.m16n8k16.row.col.f32.bf16.bf16.f32 "
        "{%0,%1,%2,%3}, {%4,%5,%6,%7}, {%8,%9}, {%0,%1,%2,%3};"
        : "+f"(c[0]), "+f"(c[1]), "+f"(c[2]), "+f"(c[3])
        : "r"(a.x), "r"(a.y), "r"(a.z), "r"(a.w), "r"(b0), "r"(b1));
}
static __device__ __forceinline__ void ldmat4(unsigned& r0, unsigned& r1,
                                              unsigned& r2, unsigned& r3, unsigned addr)
{
    asm volatile("ldmatrix.sync.aligned.m8n8.x4.shared.b16 {%0,%1,%2,%3}, [%4];"
                 : "=r"(r0), "=r"(r1), "=r"(r2), "=r"(r3) : "r"(addr));
}
static __device__ __forceinline__ uint4 ldg_cg16(const uint4* p)
{
    uint4 v;
    asm volatile("ld.global.cg.v4.u32 {%0,%1,%2,%3}, [%4];"
                 : "=r"(v.x), "=r"(v.y), "=r"(v.z), "=r"(v.w) : "l"(p));
    return v;
}

template<int NB>
static __device__ __forceinline__ void tile_compute(
    const uint4* __restrict__ ahp,
    const uint4* __restrict__ alp,
    unsigned bh_base, unsigned bl_base,
    unsigned lm_off_p0, unsigned lm_off_p1,
    float acc[4][4])
{
    #pragma unroll 4
    for (int kk = 0; kk < 16; kk++) {
        uint4 ah = __ldg(ahp);          // L1-resident (pinned rule)
        uint4 al = ldg_cg16(alp);       // L2 stream
        ahp += 32; alp += 32;
        unsigned kb = (unsigned)kk * 32;

        unsigned bh0, bh1, bh2, bh3, bl0, bl1, bl2, bl3;
        ldmat4(bh0, bh1, bh2, bh3, bh_base + lm_off_p0 + kb);
        ldmat4(bl0, bl1, bl2, bl3, bl_base + lm_off_p0 + kb);
        mma16816(acc[0], ah, bh0, bh1);
        mma16816(acc[0], ah, bl0, bl1);
        mma16816(acc[0], al, bh0, bh1);
        if (NB > 1) {
            mma16816(acc[1], ah, bh2, bh3);
            mma16816(acc[1], ah, bl2, bl3);
            mma16816(acc[1], al, bh2, bh3);
        }
        if (NB > 2) {
            unsigned ch0, ch1, ch2, ch3, cl0, cl1, cl2, cl3;
            ldmat4(ch0, ch1, ch2, ch3, bh_base + lm_off_p1 + kb);
            ldmat4(cl0, cl1, cl2, cl3, bl_base + lm_off_p1 + kb);
            mma16816(acc[2], ah, ch0, ch1);
            mma16816(acc[2], ah, cl0, cl1);
            mma16816(acc[2], al, ch0, ch1);
            if (NB > 3) {
                mma16816(acc[3], ah, ch2, ch3);
                mma16816(acc[3], ah, cl2, cl3);
                mma16816(acc[3], al, ch2, ch3);
            }
        }
    }
}

// ---------------------------------------------------------------------------
// K3: persistent levels kernel — dataflow flags + cp.async gather + prefetch
// ---------------------------------------------------------------------------
__global__ void __launch_bounds__(256, 2)
levels_kernel(const float* __restrict__ rule_b)
{
    __shared__ __align__(16) unsigned char Bh[TILE_N * BPITCH_B];
    __shared__ __align__(16) unsigned char Bl[TILE_N * BPITCH_B];
    __shared__ int s_meta[2][96];
    __shared__ int s_rdy[2][64];

    int tid  = threadIdx.x;
    int wid  = tid >> 5;
    int lane = tid & 31;
    int r    = blockIdx.x;

    unsigned bh_base = (unsigned)__cvta_generic_to_shared(Bh);
    unsigned bl_base = (unsigned)__cvta_generic_to_shared(Bl);

    int g    = lane >> 3;
    int row8 = lane & 7;
    unsigned lm_koff   = (unsigned)(g & 1) * 16;
    unsigned lm_off_p0 = (unsigned)((0 * 2 + (g >> 1)) * 8 + row8) * BPITCH_B + lm_koff;
    unsigned lm_off_p1 = (unsigned)((1 * 2 + (g >> 1)) * 8 + row8) * BPITCH_B + lm_koff;

    const uint4* ahi0 = (const uint4*)(g_WimgHi + (size_t)r * WIMG_BYTES)
                        + (size_t)wid * 512 + lane;
    const uint4* alo0 = (const uint4*)(g_WimgLo + (size_t)r * WIMG_BYTES)
                        + (size_t)wid * 512 + lane;

    int m_lo = wid * 16 + (lane >> 2);
    int m_hi = m_lo + 8;
    float bias_lo = __ldg(rule_b + r * 128 + m_lo);
    float bias_hi = __ldg(rule_b + r * 128 + m_hi);

    int ntl = g_ntiles[r];
    if (ntl == 0) return;

    // fill meta buffer b for tile index t
    auto fill_meta = [&](int t, int b) {
        int dsc  = g_tiles[r * MAXT_R + t];
        int base = dsc >> 6;
        int na   = dsc & 63;
        if (tid < TILE_N) {
            int4 pk = (tid < na) ? g_pack[base + tid] : make_int4(-1, 0, 0, 0);
            s_meta[b][tid] = pk.x; s_meta[b][32 + tid] = pk.y; s_meta[b][64 + tid] = pk.z;
        }
    };
    // one-shot flag check + safe L2 prefetch of confirmed rows
    auto precheck = [&](int b) {
        if (tid < 64) {
            int n = s_meta[b][tid & 31];
            int p = s_meta[b][32 + tid];
            int ok = 1;
            if (n >= 0 && p >= N_INIT) {
                unsigned v;
                asm volatile("ld.global.cg.u32 %0, [%1];" : "=r"(v)
                             : "l"(&g_ready[p - N_INIT]));
                ok = (v != 0);
            }
            s_rdy[b][tid] = ok;
            if (ok && n >= 0) {
                const char* ph = (const char*)(g_hi + (size_t)p * D);
                const char* pl = (const char*)(g_lo + (size_t)p * D);
                asm volatile("prefetch.global.L2 [%0];" :: "l"(ph));
                asm volatile("prefetch.global.L2 [%0];" :: "l"(ph + 128));
                asm volatile("prefetch.global.L2 [%0];" :: "l"(pl));
                asm volatile("prefetch.global.L2 [%0];" :: "l"(pl + 128));
            }
        }
    };

    // prologue: tile 0 meta + precheck
    fill_meta(0, 0);
    __syncthreads();
    precheck(0);

    for (int t = 0; t < ntl; t++) {
        int cur = t & 1, nxt = cur ^ 1;
        const int* mc = s_meta[cur];
        int dsc  = g_tiles[r * MAXT_R + t];
        int nact = dsc & 63;

        // a) blocking wait for unconfirmed parents (R12 protocol)
        if (tid < 64) {
            if (!s_rdy[cur][tid]) {
                int p = mc[32 + tid];
                const unsigned* f = &g_ready[p - N_INIT];
                unsigned v;
                for (;;) {
                    asm volatile("ld.global.cg.u32 %0, [%1];" : "=r"(v) : "l"(f));
                    if (v) break;
                    __nanosleep(20);
                }
            }
        }
        __syncthreads();

        // c) cp.async gather from hi/lo planes (pure byte copy)
        {
            int s = tid >> 3, seg = tid & 7;
            int n = mc[s];
            if (n >= 0) {
                int p = (seg < 4) ? mc[32 + s] : mc[64 + s];
                int q = seg & 3, h = seg >> 2;
                const char* sh = (const char*)(g_hi + (size_t)p * D) + q * 64;
                const char* sl = (const char*)(g_lo + (size_t)p * D) + q * 64;
                unsigned dh = bh_base + s * BPITCH_B + h * 256 + q * 64;
                unsigned dl = bl_base + s * BPITCH_B + h * 256 + q * 64;
                #pragma unroll
                for (int i = 0; i < 4; i++) {
                    asm volatile("cp.async.cg.shared.global [%0], [%1], 16;"
                                 :: "r"(dh + i * 16), "l"(sh + i * 16));
                    asm volatile("cp.async.cg.shared.global [%0], [%1], 16;"
                                 :: "r"(dl + i * 16), "l"(sl + i * 16));
                }
            }
            asm volatile("cp.async.commit_group;" ::: "memory");
        }

        // d) fill next tile's meta while cp.async is in flight
        if (t + 1 < ntl) fill_meta(t + 1, nxt);

        // e) gather landed
        asm volatile("cp.async.wait_group 0;" ::: "memory");
        __syncthreads();

        // f) non-blocking precheck + safe prefetch for next tile
        if (t + 1 < ntl) precheck(nxt);

        // g) compute
        {
            float acc[4][4];
            #pragma unroll
            for (int nb = 0; nb < 4; nb++)
                #pragma unroll
                for (int q = 0; q < 4; q++) acc[nb][q] = 0.0f;

            int nblk = (nact + 7) >> 3;
            switch (nblk) {
                case 4: tile_compute<4>(ahi0, alo0, bh_base, bl_base, lm_off_p0, lm_off_p1, acc); break;
                case 3: tile_compute<3>(ahi0, alo0, bh_base, bl_base, lm_off_p0, lm_off_p1, acc); break;
                case 2: tile_compute<2>(ahi0, alo0, bh_base, bl_base, lm_off_p0, lm_off_p1, acc); break;
                default: tile_compute<1>(ahi0, alo0, bh_base, bl_base, lm_off_p0, lm_off_p1, acc); break;
            }

            // h) stores: fp32 + hi/lo planes
            #pragma unroll
            for (int nb = 0; nb < 4; nb++) {
                if (nb < nblk) {
                    int n0 = nb * 8 + (lane & 3) * 2;
                    int j0 = mc[n0], j1 = mc[n0 + 1];
                    if (j0 >= 0) {
                        float x0 = fmaxf(acc[nb][0] + bias_lo, 0.f);
                        float x2 = fmaxf(acc[nb][2] + bias_hi, 0.f);
                        g_store[(size_t)j0 * D + m_lo] = x0;
                        g_store[(size_t)j0 * D + m_hi] = x2;
                        float h0 = bf16_hi_part(x0), h2 = bf16_hi_part(x2);
                        g_hi[(size_t)j0 * D + m_lo] = bf16_us(x0);
                        g_hi[(size_t)j0 * D + m_hi] = bf16_us(x2);
                        g_lo[(size_t)j0 * D + m_lo] = bf16_us(x0 - h0);
                        g_lo[(size_t)j0 * D + m_hi] = bf16_us(x2 - h2);
                    }
                    if (j1 >= 0) {
                        float x1 = fmaxf(acc[nb][1] + bias_lo, 0.f);
                        float x3 = fmaxf(acc[nb][3] + bias_hi, 0.f);
                        g_store[(size_t)j1 * D + m_lo] = x1;
                        g_store[(size_t)j1 * D + m_hi] = x3;
                        float h1 = bf16_hi_part(x1), h3 = bf16_hi_part(x3);
                        g_hi[(size_t)j1 * D + m_lo] = bf16_us(x1);
                        g_hi[(size_t)j1 * D + m_hi] = bf16_us(x3);
                        g_lo[(size_t)j1 * D + m_lo] = bf16_us(x1 - h1);
                        g_lo[(size_t)j1 * D + m_hi] = bf16_us(x3 - h3);
                    }
                }
            }
        }

        // publish flags
        __threadfence();
        __syncthreads();
        if (tid < TILE_N) {
            int n = mc[tid];
            if (n >= 0) {
                asm volatile("st.global.cg.u32 [%0], %1;"
                             :: "l"(&g_ready[n - N_INIT]), "r"(1u) : "memory");
            }
        }
        __syncthreads();
    }
}

// ---------------------------------------------------------------------------
// K4: eval + partial reductions (unchanged, reads fp32 g_store)
// ---------------------------------------------------------------------------
__global__ void eval_kernel(const float* __restrict__ eval_w,
                            const float* __restrict__ eval_b,
                            const float* __restrict__ pos_vals,
                            const float* __restrict__ neg_vals)
{
    __shared__ float4 sw[32];
    __shared__ float  wacc[8][6];
    if (threadIdx.x < 32) sw[threadIdx.x] = ((const float4*)eval_w)[threadIdx.x];
    __syncthreads();

    int wid  = threadIdx.x >> 5;
    int lane = threadIdx.x & 31;
    int gw     = blockIdx.x * 8 + wid;
    int nwarps = EVAL_BLOCKS * 8;
    float eb = eval_b[0];
    float4 w4 = sw[lane];

    float A = 0.f, B = 0.f, pok = 0.f, nok = 0.f, spv = 0.f, snv = 0.f;

    for (size_t node = gw; node < (size_t)N_TOT; node += nwarps) {
        float4 v = ((const float4*)(g_store + node * D))[lane];
        float d = v.x * w4.x + v.y * w4.y + v.z * w4.z + v.w * w4.w;
        #pragma unroll
        for (int off = 16; off; off >>= 1) d += __shfl_down_sync(0xffffffffu, d, off);
        if (lane == 0) {
            float l  = d + eb;
            float pv = pos_vals[node], nv = neg_vals[node];
            float spn = log1pf(expf(-fabsf(l)));
            float sp_pos = spn + fmaxf(l, 0.f);
            float sp_neg = spn + fmaxf(-l, 0.f);
            A += pv * sp_neg;
            B += nv * sp_pos;
            if (l >= 0.f) pok += pv; else nok += nv;
            spv += pv;
            snv += nv;
        }
    }

    if (lane == 0) {
        wacc[wid][0] = A;   wacc[wid][1] = B;
        wacc[wid][2] = pok; wacc[wid][3] = nok;
        wacc[wid][4] = spv; wacc[wid][5] = snv;
    }
    __syncthreads();
    if (threadIdx.x == 0) {
        float o[6] = {0, 0, 0, 0, 0, 0};
        for (int w = 0; w < 8; w++)
            for (int k = 0; k < 6; k++) o[k] += wacc[w][k];
        for (int k = 0; k < 6; k++) g_partial[blockIdx.x * 6 + k] = o[k];
    }
}

__global__ void final_kernel(float* __restrict__ out)
{
    if (blockIdx.x == 0 && threadIdx.x == 0) {
        float A = 0.f, B = 0.f, pok = 0.f, nok = 0.f, spv = 0.f, snv = 0.f;
        for (int b = 0; b < EVAL_BLOCKS; b++) {
            A   += g_partial[b * 6 + 0];
            B   += g_partial[b * 6 + 1];
            pok += g_partial[b * 6 + 2];
            nok += g_partial[b * 6 + 3];
            spv += g_partial[b * 6 + 4];
            snv += g_partial[b * 6 + 5];
        }
        float pw = snv / spv;
        out[0] = pw * A + B;
        out[1] = pok;
        out[2] = nok;
    }
}

// ---------------------------------------------------------------------------
extern "C" void kernel_launch(void* const* d_in, const int* in_sizes, int n_in,
                              void* d_out, int out_size)
{
    const float* thax_table = (const float*)d_in[0];
    const float* sine_table = (const float*)d_in[1];
    const float* rule_W     = (const float*)d_in[2];
    const float* rule_b     = (const float*)d_in[3];
    const float* eval_w     = (const float*)d_in[4];
    const float* eval_b     = (const float*)d_in[5];
    const float* pos_vals   = (const float*)d_in[6];
    const float* neg_vals   = (const float*)d_in[7];
    const int*   init_thax  = (const int*)d_in[8];
    const int*   init_sine  = (const int*)d_in[9];
    const int*   parents    = (const int*)d_in[10];
    const int*   rules      = (const int*)d_in[11];

    (void)in_sizes; (void)n_in; (void)out_size;

    cudaFuncSetAttribute(convw_kernel,
                         cudaFuncAttributeMaxDynamicSharedMemorySize, 131072);

    init_embed_kernel<<<2048, 256>>>((const float4*)thax_table,
                                     (const float4*)sine_table,
                                     init_thax, init_sine);
    convw_kernel<<<N_RULES, 256, 131072>>>(rule_W);
    group_kernel<<<LVLS, 256>>>(rules, parents);
    tiles_kernel<<<1, 256>>>();
    levels_kernel<<<NCTA, 256>>>(rule_b);
    eval_kernel<<<EVAL_BLOCKS, 256>>>(eval_w, eval_b, pos_vals, neg_vals);
    final_kernel<<<1, 32>>>((float*)d_out);
}

// round 16
// speedup vs baseline: 1.6700x; 1.0083x over previous
#include <cuda_runtime.h>
#include <cuda_bf16.h>
#include <cstdint>

#define D        128
#define N_INIT   100000
#define LVLS     64
#define M        4096
#define N_RULES  256
#define N_TOT    (N_INIT + LVLS * M)
#define N_DERIV  (LVLS * M)

#define NCTA     256           // persistent CTAs = rules, 2 per SM, single wave
#define TILE_N   32
#define MAXT_R   96            // max tiles per rule
#define EVAL_BLOCKS 1024

#define BPITCH_B 528
#define WIMG_BYTES 65536

__device__ float g_store[(size_t)N_TOT * D];
__device__ __align__(16) unsigned short g_hi[(size_t)N_TOT * D];
__device__ __align__(16) unsigned short g_lo[(size_t)N_TOT * D];
__device__ int   g_order[LVLS * M];
__device__ int   g_ruleoff[LVLS * (N_RULES + 1)];
__device__ int4  g_pack[LVLS * M];               // (global node, p0, p1, 0)
__device__ int   g_tiles[N_RULES * MAXT_R];      // (slotbase << 6) | nact
__device__ int   g_ntiles[N_RULES];
__device__ unsigned g_ready[N_DERIV];
__device__ float g_partial[EVAL_BLOCKS * 6];
__device__ unsigned char g_WimgHi[(size_t)N_RULES * WIMG_BYTES];
__device__ unsigned char g_WimgLo[(size_t)N_RULES * WIMG_BYTES];

static __device__ __forceinline__ unsigned pack_bf16x2(float lo, float hi) {
    unsigned short a = __bfloat16_as_ushort(__float2bfloat16_rn(lo));
    unsigned short b = __bfloat16_as_ushort(__float2bfloat16_rn(hi));
    return (unsigned)a | ((unsigned)b << 16);
}
static __device__ __forceinline__ float bf16_hi_part(float v) {
    return __bfloat162float(__float2bfloat16_rn(v));
}
static __device__ __forceinline__ unsigned short bf16_us(float v) {
    return __bfloat16_as_ushort(__float2bfloat16_rn(v));
}

// ---------------------------------------------------------------------------
// K1: init embeddings (warp per node) + hi/lo planes
// ---------------------------------------------------------------------------
__global__ void init_embed_kernel(const float4* __restrict__ thax,
                                  const float4* __restrict__ sine,
                                  const int* __restrict__ it,
                                  const int* __restrict__ is)
{
    int wid  = threadIdx.x >> 5;
    int lane = threadIdx.x & 31;
    int gw     = blockIdx.x * 8 + wid;
    int nwarps = gridDim.x * 8;
    float4* st = (float4*)g_store;

    for (int i = gw; i < N_INIT; i += nwarps) {
        float4 a = thax[(size_t)__ldg(it + i) * 32 + lane];
        float4 b = sine[(size_t)__ldg(is + i) * 32 + lane];
        float4 e = make_float4(a.x + b.x, a.y + b.y, a.z + b.z, a.w + b.w);
        st[(size_t)i * 32 + lane] = e;
        float hx = bf16_hi_part(e.x), hy = bf16_hi_part(e.y);
        float hz = bf16_hi_part(e.z), hw = bf16_hi_part(e.w);
        *(uint2*)(g_hi + (size_t)i * D + lane * 4) =
            make_uint2(pack_bf16x2(hx, hy), pack_bf16x2(hz, hw));
        *(uint2*)(g_lo + (size_t)i * D + lane * 4) =
            make_uint2(pack_bf16x2(e.x - hx, e.y - hy), pack_bf16x2(e.z - hz, e.w - hw));
    }
}

// ---------------------------------------------------------------------------
// K1b: convert rule_W -> fragment-ordered bf16 hi/lo images
// ---------------------------------------------------------------------------
__global__ void convw_kernel(const float* __restrict__ rule_W)
{
    extern __shared__ float Wsm[];            // [256][128]
    int r   = blockIdx.x;
    int tid = threadIdx.x;

    const float4* src = (const float4*)(rule_W + (size_t)r * 32768);
    #pragma unroll 4
    for (int i = tid; i < 8192; i += 256) ((float4*)Wsm)[i] = __ldg(src + i);
    __syncthreads();

    unsigned char* dh = g_WimgHi + (size_t)r * WIMG_BYTES;
    unsigned char* dl = g_WimgLo + (size_t)r * WIMG_BYTES;
    for (int idx = tid; idx < 4096; idx += 256) {
        int lane = idx & 31, kk = (idx >> 5) & 15, w = idx >> 9;
        int m0 = w * 16 + (lane >> 2);
        int k0 = kk * 16 + (lane & 3) * 2;

        float v[8];
        v[0] = Wsm[(k0)     * 128 + m0];     v[1] = Wsm[(k0 + 1) * 128 + m0];
        v[2] = Wsm[(k0)     * 128 + m0 + 8]; v[3] = Wsm[(k0 + 1) * 128 + m0 + 8];
        v[4] = Wsm[(k0 + 8) * 128 + m0];     v[5] = Wsm[(k0 + 9) * 128 + m0];
        v[6] = Wsm[(k0 + 8) * 128 + m0 + 8]; v[7] = Wsm[(k0 + 9) * 128 + m0 + 8];

        unsigned h[4], l[4];
        #pragma unroll
        for (int j = 0; j < 4; j++) {
            float h0 = bf16_hi_part(v[2*j]),   h1 = bf16_hi_part(v[2*j+1]);
            h[j] = pack_bf16x2(h0, h1);
            l[j] = pack_bf16x2(v[2*j] - h0, v[2*j+1] - h1);
        }
        *(uint4*)(dh + (size_t)idx * 16) = make_uint4(h[0], h[1], h[2], h[3]);
        *(uint4*)(dl + (size_t)idx * 16) = make_uint4(l[0], l[1], l[2], l[3]);
    }
}

// ---------------------------------------------------------------------------
// K2: group by rule + pack (global node, p0, p1) + offsets + zero flags
// ---------------------------------------------------------------------------
__global__ void group_kernel(const int* __restrict__ rules,
                             const int* __restrict__ parents)
{
    int lvl = blockIdx.x;
    int tid = threadIdx.x;
    __shared__ int counts[N_RULES];
    __shared__ int offs[N_RULES + 1];
    __shared__ int cursor[N_RULES];

    for (int j = tid; j < M; j += blockDim.x) g_ready[lvl * M + j] = 0;

    for (int r = tid; r < N_RULES; r += blockDim.x) counts[r] = 0;
    __syncthreads();
    for (int j = tid; j < M; j += blockDim.x)
        atomicAdd(&counts[rules[lvl * M + j]], 1);
    __syncthreads();
    if (tid == 0) {
        int s = 0;
        for (int r = 0; r < N_RULES; r++) { offs[r] = s; s += counts[r]; }
        offs[N_RULES] = s;
    }
    __syncthreads();
    for (int r = tid; r < N_RULES; r += blockDim.x) cursor[r] = offs[r];
    for (int r = tid; r <= N_RULES; r += blockDim.x)
        g_ruleoff[lvl * (N_RULES + 1) + r] = offs[r];
    __syncthreads();
    for (int j = tid; j < M; j += blockDim.x) {
        int r = rules[lvl * M + j];
        int p = atomicAdd(&cursor[r], 1);
        g_order[lvl * M + p] = j;
    }
    __syncthreads();

    for (int slot = tid; slot < M; slot += blockDim.x) {
        int j = g_order[lvl * M + slot];
        int4 pk;
        pk.x = N_INIT + lvl * M + j;             // global node id
        pk.y = parents[((size_t)lvl * M + j) * 2 + 0];
        pk.z = parents[((size_t)lvl * M + j) * 2 + 1];
        pk.w = 0;
        g_pack[lvl * M + slot] = pk;
    }
}

// K2b: flat per-rule tile list — PARALLEL (one CTA per rule, thread per level)
__global__ void tiles_kernel()
{
    __shared__ int s_cnt[LVLS];
    __shared__ int s_off[LVLS];
    int r   = blockIdx.x;
    int lvl = threadIdx.x;       // 64 threads

    int st = g_ruleoff[lvl * (N_RULES + 1) + r];
    int en = g_ruleoff[lvl * (N_RULES + 1) + r + 1];
    int nt = (en - st + TILE_N - 1) / TILE_N;
    s_cnt[lvl] = nt;
    __syncthreads();
    if (lvl == 0) {
        int s = 0;
        #pragma unroll
        for (int l = 0; l < LVLS; l++) { s_off[l] = s; s += s_cnt[l]; }
        g_ntiles[r] = s;
    }
    __syncthreads();
    int o = s_off[lvl];
    for (int i = 0; i < nt; i++) {
        int tb = st + i * TILE_N;
        int na = min(TILE_N, en - tb);
        g_tiles[r * MAXT_R + o + i] = ((lvl * M + tb) << 6) | na;
    }
}

// ---------------------------------------------------------------------------
// mma helpers
// ---------------------------------------------------------------------------
static __device__ __forceinline__ void mma16816(float* c, const uint4& a,
                                                unsigned b0, unsigned b1)
{
    asm volatile(
        "mma.sync.aligned.m16n8k16.row.col.f32.bf16.bf16.f32 "
        "{%0,%1,%2,%3}, {%4,%5,%6,%7}, {%8,%9}, {%0,%1,%2,%3};"
        : "+f"(c[0]), "+f"(c[1]), "+f"(c[2]), "+f"(c[3])
        : "r"(a.x), "r"(a.y), "r"(a.z), "r"(a.w), "r"(b0), "r"(b1));
}
static __device__ __forceinline__ void ldmat4(unsigned& r0, unsigned& r1,
                                              unsigned& r2, unsigned& r3, unsigned addr)
{
    asm volatile("ldmatrix.sync.aligned.m8n8.x4.shared.b16 {%0,%1,%2,%3}, [%4];"
                 : "=r"(r0), "=r"(r1), "=r"(r2), "=r"(r3) : "r"(addr));
}
static __device__ __forceinline__ uint4 ldg_cg16(const uint4* p)
{
    uint4 v;
    asm volatile("ld.global.cg.v4.u32 {%0,%1,%2,%3}, [%4];"
                 : "=r"(v.x), "=r"(v.y), "=r"(v.z), "=r"(v.w) : "l"(p));
    return v;
}

template<int NB>
static __device__ __forceinline__ void tile_compute(
    const uint4* __restrict__ ahp,
    const uint4* __restrict__ alp,
    unsigned bh_base, unsigned bl_base,
    unsigned lm_off_p0, unsigned lm_off_p1,
    float acc[4][4])
{
    #pragma unroll 4
    for (int kk = 0; kk < 16; kk++) {
        uint4 ah = __ldg(ahp);          // L1-resident (pinned rule)
        uint4 al = ldg_cg16(alp);       // L2 stream
        ahp += 32; alp += 32;
        unsigned kb = (unsigned)kk * 32;

        unsigned bh0, bh1, bh2, bh3, bl0, bl1, bl2, bl3;
        ldmat4(bh0, bh1, bh2, bh3, bh_base + lm_off_p0 + kb);
        ldmat4(bl0, bl1, bl2, bl3, bl_base + lm_off_p0 + kb);
        mma16816(acc[0], ah, bh0, bh1);
        mma16816(acc[0], ah, bl0, bl1);
        mma16816(acc[0], al, bh0, bh1);
        if (NB > 1) {
            mma16816(acc[1], ah, bh2, bh3);
            mma16816(acc[1], ah, bl2, bl3);
            mma16816(acc[1], al, bh2, bh3);
        }
        if (NB > 2) {
            unsigned ch0, ch1, ch2, ch3, cl0, cl1, cl2, cl3;
            ldmat4(ch0, ch1, ch2, ch3, bh_base + lm_off_p1 + kb);
            ldmat4(cl0, cl1, cl2, cl3, bl_base + lm_off_p1 + kb);
            mma16816(acc[2], ah, ch0, ch1);
            mma16816(acc[2], ah, cl0, cl1);
            mma16816(acc[2], al, ch0, ch1);
            if (NB > 3) {
                mma16816(acc[3], ah, ch2, ch3);
                mma16816(acc[3], ah, cl2, cl3);
                mma16816(acc[3], al, ch2, ch3);
            }
        }
    }
}

// ---------------------------------------------------------------------------
// K3: persistent levels kernel — dataflow flags + cp.async gather + prefetch
// ---------------------------------------------------------------------------
__global__ void __launch_bounds__(256, 2)
levels_kernel(const float* __restrict__ rule_b)
{
    __shared__ __align__(16) unsigned char Bh[TILE_N * BPITCH_B];
    __shared__ __align__(16) unsigned char Bl[TILE_N * BPITCH_B];
    __shared__ int s_meta[2][96];
    __shared__ int s_rdy[2][64];

    int tid  = threadIdx.x;
    int wid  = tid >> 5;
    int lane = tid & 31;
    int r    = blockIdx.x;

    unsigned bh_base = (unsigned)__cvta_generic_to_shared(Bh);
    unsigned bl_base = (unsigned)__cvta_generic_to_shared(Bl);

    int g    = lane >> 3;
    int row8 = lane & 7;
    unsigned lm_koff   = (unsigned)(g & 1) * 16;
    unsigned lm_off_p0 = (unsigned)((0 * 2 + (g >> 1)) * 8 + row8) * BPITCH_B + lm_koff;
    unsigned lm_off_p1 = (unsigned)((1 * 2 + (g >> 1)) * 8 + row8) * BPITCH_B + lm_koff;

    const uint4* ahi0 = (const uint4*)(g_WimgHi + (size_t)r * WIMG_BYTES)
                        + (size_t)wid * 512 + lane;
    const uint4* alo0 = (const uint4*)(g_WimgLo + (size_t)r * WIMG_BYTES)
                        + (size_t)wid * 512 + lane;

    int m_lo = wid * 16 + (lane >> 2);
    int m_hi = m_lo + 8;
    float bias_lo = __ldg(rule_b + r * 128 + m_lo);
    float bias_hi = __ldg(rule_b + r * 128 + m_hi);

    int ntl = g_ntiles[r];
    if (ntl == 0) return;

    auto fill_meta = [&](int t, int b) {
        int dsc  = g_tiles[r * MAXT_R + t];
        int base = dsc >> 6;
        int na   = dsc & 63;
        if (tid < TILE_N) {
            int4 pk = (tid < na) ? g_pack[base + tid] : make_int4(-1, 0, 0, 0);
            s_meta[b][tid] = pk.x; s_meta[b][32 + tid] = pk.y; s_meta[b][64 + tid] = pk.z;
        }
    };
    auto precheck = [&](int b) {
        if (tid < 64) {
            int n = s_meta[b][tid & 31];
            int p = s_meta[b][32 + tid];
            int ok = 1;
            if (n >= 0 && p >= N_INIT) {
                unsigned v;
                asm volatile("ld.global.cg.u32 %0, [%1];" : "=r"(v)
                             : "l"(&g_ready[p - N_INIT]));
                ok = (v != 0);
            }
            s_rdy[b][tid] = ok;
            if (ok && n >= 0) {
                const char* ph = (const char*)(g_hi + (size_t)p * D);
                const char* pl = (const char*)(g_lo + (size_t)p * D);
                asm volatile("prefetch.global.L2 [%0];" :: "l"(ph));
                asm volatile("prefetch.global.L2 [%0];" :: "l"(ph + 128));
                asm volatile("prefetch.global.L2 [%0];" :: "l"(pl));
                asm volatile("prefetch.global.L2 [%0];" :: "l"(pl + 128));
            }
        }
    };

    fill_meta(0, 0);
    __syncthreads();
    precheck(0);

    for (int t = 0; t < ntl; t++) {
        int cur = t & 1, nxt = cur ^ 1;
        const int* mc = s_meta[cur];
        int dsc  = g_tiles[r * MAXT_R + t];
        int nact = dsc & 63;

        // blocking wait for unconfirmed parents
        if (tid < 64) {
            if (!s_rdy[cur][tid]) {
                int p = mc[32 + tid];
                const unsigned* f = &g_ready[p - N_INIT];
                unsigned v;
                for (;;) {
                    asm volatile("ld.global.cg.u32 %0, [%1];" : "=r"(v) : "l"(f));
                    if (v) break;
                    __nanosleep(20);
                }
            }
        }
        __syncthreads();

        // cp.async gather from hi/lo planes (pure byte copy)
        {
            int s = tid >> 3, seg = tid & 7;
            int n = mc[s];
            if (n >= 0) {
                int p = (seg < 4) ? mc[32 + s] : mc[64 + s];
                int q = seg & 3, h = seg >> 2;
                const char* sh = (const char*)(g_hi + (size_t)p * D) + q * 64;
                const char* sl = (const char*)(g_lo + (size_t)p * D) + q * 64;
                unsigned dh = bh_base + s * BPITCH_B + h * 256 + q * 64;
                unsigned dl = bl_base + s * BPITCH_B + h * 256 + q * 64;
                #pragma unroll
                for (int i = 0; i < 4; i++) {
                    asm volatile("cp.async.cg.shared.global [%0], [%1], 16;"
                                 :: "r"(dh + i * 16), "l"(sh + i * 16));
                    asm volatile("cp.async.cg.shared.global [%0], [%1], 16;"
                                 :: "r"(dl + i * 16), "l"(sl + i * 16));
                }
            }
            asm volatile("cp.async.commit_group;" ::: "memory");
        }

        if (t + 1 < ntl) fill_meta(t + 1, nxt);

        asm volatile("cp.async.wait_group 0;" ::: "memory");
        __syncthreads();

        if (t + 1 < ntl) precheck(nxt);

        // compute
        {
            float acc[4][4];
            #pragma unroll
            for (int nb = 0; nb < 4; nb++)
                #pragma unroll
                for (int q = 0; q < 4; q++) acc[nb][q] = 0.0f;

            int nblk = (nact + 7) >> 3;
            switch (nblk) {
                case 4: tile_compute<4>(ahi0, alo0, bh_base, bl_base, lm_off_p0, lm_off_p1, acc); break;
                case 3: tile_compute<3>(ahi0, alo0, bh_base, bl_base, lm_off_p0, lm_off_p1, acc); break;
                case 2: tile_compute<2>(ahi0, alo0, bh_base, bl_base, lm_off_p0, lm_off_p1, acc); break;
                default: tile_compute<1>(ahi0, alo0, bh_base, bl_base, lm_off_p0, lm_off_p1, acc); break;
            }

            #pragma unroll
            for (int nb = 0; nb < 4; nb++) {
                if (nb < nblk) {
                    int n0 = nb * 8 + (lane & 3) * 2;
                    int j0 = mc[n0], j1 = mc[n0 + 1];
                    if (j0 >= 0) {
                        float x0 = fmaxf(acc[nb][0] + bias_lo, 0.f);
                        float x2 = fmaxf(acc[nb][2] + bias_hi, 0.f);
                        g_store[(size_t)j0 * D + m_lo] = x0;
                        g_store[(size_t)j0 * D + m_hi] = x2;
                        float h0 = bf16_hi_part(x0), h2 = bf16_hi_part(x2);
                        g_hi[(size_t)j0 * D + m_lo] = bf16_us(x0);
                        g_hi[(size_t)j0 * D + m_hi] = bf16_us(x2);
                        g_lo[(size_t)j0 * D + m_lo] = bf16_us(x0 - h0);
                        g_lo[(size_t)j0 * D + m_hi] = bf16_us(x2 - h2);
                    }
                    if (j1 >= 0) {
                        float x1 = fmaxf(acc[nb][1] + bias_lo, 0.f);
                        float x3 = fmaxf(acc[nb][3] + bias_hi, 0.f);
                        g_store[(size_t)j1 * D + m_lo] = x1;
                        g_store[(size_t)j1 * D + m_hi] = x3;
                        float h1 = bf16_hi_part(x1), h3 = bf16_hi_part(x3);
                        g_hi[(size_t)j1 * D + m_lo] = bf16_us(x1);
                        g_hi[(size_t)j1 * D + m_hi] = bf16_us(x3);
                        g_lo[(size_t)j1 * D + m_lo] = bf16_us(x1 - h1);
                        g_lo[(size_t)j1 * D + m_hi] = bf16_us(x3 - h3);
                    }
                }
            }
        }

        __threadfence();
        __syncthreads();
        if (tid < TILE_N) {
            int n = mc[tid];
            if (n >= 0) {
                asm volatile("st.global.cg.u32 [%0], %1;"
                             :: "l"(&g_ready[n - N_INIT]), "r"(1u) : "memory");
            }
        }
        __syncthreads();
    }
}

// ---------------------------------------------------------------------------
// K4: eval — 2x unrolled, .cg loads, same accumulation order (bit-identical)
// ---------------------------------------------------------------------------
__global__ void eval_kernel(const float* __restrict__ eval_w,
                            const float* __restrict__ eval_b,
                            const float* __restrict__ pos_vals,
                            const float* __restrict__ neg_vals)
{
    __shared__ float4 sw[32];
    __shared__ float  wacc[8][6];
    if (threadIdx.x < 32) sw[threadIdx.x] = ((const float4*)eval_w)[threadIdx.x];
    __syncthreads();

    int wid  = threadIdx.x >> 5;
    int lane = threadIdx.x & 31;
    size_t gw     = blockIdx.x * 8 + wid;
    size_t nwarps = EVAL_BLOCKS * 8;
    float eb = eval_b[0];
    float4 w4 = sw[lane];

    float A = 0.f, B = 0.f, pok = 0.f, nok = 0.f, spv = 0.f, snv = 0.f;

    auto accum = [&](size_t node, float d) {
        #pragma unroll
        for (int off = 16; off; off >>= 1) d += __shfl_down_sync(0xffffffffu, d, off);
        if (lane == 0) {
            float l  = d + eb;
            float pv = pos_vals[node], nv = neg_vals[node];
            float spn = log1pf(expf(-fabsf(l)));
            float sp_pos = spn + fmaxf(l, 0.f);
            float sp_neg = spn + fmaxf(-l, 0.f);
            A += pv * sp_neg;
            B += nv * sp_pos;
            if (l >= 0.f) pok += pv; else nok += nv;
            spv += pv;
            snv += nv;
        }
    };

    size_t node = gw;
    for (; node + nwarps < (size_t)N_TOT; node += 2 * nwarps) {
        const float4* s0 = (const float4*)(g_store + node * D) + lane;
        const float4* s1 = (const float4*)(g_store + (node + nwarps) * D) + lane;
        float4 v0, v1;
        asm volatile("ld.global.cg.v4.f32 {%0,%1,%2,%3}, [%4];"
                     : "=f"(v0.x), "=f"(v0.y), "=f"(v0.z), "=f"(v0.w) : "l"(s0));
        asm volatile("ld.global.cg.v4.f32 {%0,%1,%2,%3}, [%4];"
                     : "=f"(v1.x), "=f"(v1.y), "=f"(v1.z), "=f"(v1.w) : "l"(s1));
        accum(node,          v0.x * w4.x + v0.y * w4.y + v0.z * w4.z + v0.w * w4.w);
        accum(node + nwarps, v1.x * w4.x + v1.y * w4.y + v1.z * w4.z + v1.w * w4.w);
    }
    for (; node < (size_t)N_TOT; node += nwarps) {
        float4 v = ((const float4*)(g_store + node * D))[lane];
        accum(node, v.x * w4.x + v.y * w4.y + v.z * w4.z + v.w * w4.w);
    }

    if (lane == 0) {
        wacc[wid][0] = A;   wacc[wid][1] = B;
        wacc[wid][2] = pok; wacc[wid][3] = nok;
        wacc[wid][4] = spv; wacc[wid][5] = snv;
    }
    __syncthreads();
    if (threadIdx.x == 0) {
        float o[6] = {0, 0, 0, 0, 0, 0};
        for (int w = 0; w < 8; w++)
            for (int k = 0; k < 6; k++) o[k] += wacc[w][k];
        for (int k = 0; k < 6; k++) g_partial[blockIdx.x * 6 + k] = o[k];
    }
}

__global__ void final_kernel(float* __restrict__ out)
{
    if (blockIdx.x == 0 && threadIdx.x == 0) {
        float A = 0.f, B = 0.f, pok = 0.f, nok = 0.f, spv = 0.f, snv = 0.f;
        for (int b = 0; b < EVAL_BLOCKS; b++) {
            A   += g_partial[b * 6 + 0];
            B   += g_partial[b * 6 + 1];
            pok += g_partial[b * 6 + 2];
            nok += g_partial[b * 6 + 3];
            spv += g_partial[b * 6 + 4];
            snv += g_partial[b * 6 + 5];
        }
        float pw = snv / spv;
        out[0] = pw * A + B;
        out[1] = pok;
        out[2] = nok;
    }
}

// ---------------------------------------------------------------------------
extern "C" void kernel_launch(void* const* d_in, const int* in_sizes, int n_in,
                              void* d_out, int out_size)
{
    const float* thax_table = (const float*)d_in[0];
    const float* sine_table = (const float*)d_in[1];
    const float* rule_W     = (const float*)d_in[2];
    const float* rule_b     = (const float*)d_in[3];
    const float* eval_w     = (const float*)d_in[4];
    const float* eval_b     = (const float*)d_in[5];
    const float* pos_vals   = (const float*)d_in[6];
    const float* neg_vals   = (const float*)d_in[7];
    const int*   init_thax  = (const int*)d_in[8];
    const int*   init_sine  = (const int*)d_in[9];
    const int*   parents    = (const int*)d_in[10];
    const int*   rules      = (const int*)d_in[11];

    (void)in_sizes; (void)n_in; (void)out_size;

    cudaFuncSetAttribute(convw_kernel,
                         cudaFuncAttributeMaxDynamicSharedMemorySize, 131072);

    init_embed_kernel<<<2048, 256>>>((const float4*)thax_table,
                                     (const float4*)sine_table,
                                     init_thax, init_sine);
    convw_kernel<<<N_RULES, 256, 131072>>>(rule_W);
    group_kernel<<<LVLS, 256>>>(rules, parents);
    tiles_kernel<<<N_RULES, LVLS>>>();
    levels_kernel<<<NCTA, 256>>>(rule_b);
    eval_kernel<<<EVAL_BLOCKS, 256>>>(eval_w, eval_b, pos_vals, neg_vals);
    final_kernel<<<1, 32>>>((float*)d_out);
}